// round 10
// baseline (speedup 1.0000x reference)
#include <cuda_runtime.h>
#include <math.h>

#define NB    32     // batch
#define LSEQ  1024
#define CH    34
#define D     256
#define NE    8
#define NP    4      // only first 4 patches survive the [:, :seq_len] slice
#define PL    16
#define PRED  96

// Scratch (device globals — no allocation allowed).
__device__ float g_red[NB][8][2];             // per-segment partial sums
__device__ float g_sink[4];                   // dead store target (never read)
__device__ __align__(16) float g_partial[NB][NE][NP * D];

// ---------------------------------------------------------------------------
// cp.async helpers (LDGSTS)
// ---------------------------------------------------------------------------
__device__ __forceinline__ void cp16(void* dst_smem, const void* src) {
    unsigned saddr = (unsigned)__cvta_generic_to_shared(dst_smem);
    asm volatile("cp.async.cg.shared.global [%0], [%1], 16;\n"
                 :: "r"(saddr), "l"(src));
}
#define CP_COMMIT()  asm volatile("cp.async.commit_group;\n" ::: "memory")
#define CP_WAIT(n)   asm volatile("cp.async.wait_group %0;\n" :: "n"(n) : "memory")

// ---------------------------------------------------------------------------
// K0: wide partial stats over x[b,:,2] + L2 warm of W_experts / W_head.
// grid = 256 blocks (b*8 + seg), 128 threads.
// ---------------------------------------------------------------------------
__global__ void __launch_bounds__(128)
k0_stats(const float* __restrict__ x,
         const float* __restrict__ W_experts,
         const float* __restrict__ W_head) {
    const int blk = blockIdx.x;
    const int b   = blk >> 3;
    const int seg = blk & 7;
    const int tid  = threadIdx.x;
    const int warp = tid >> 5;
    const int lane = tid & 31;

    __shared__ float sred[8];

    const float v = x[(size_t)b * LSEQ * CH + (size_t)(seg * 128 + tid) * CH + 2];

    // L2 warm (independent loads, overlap with x latency)
    float acc = 0.f;
    {
        const float4* we4 = reinterpret_cast<const float4*>(W_experts);
        #pragma unroll
        for (int i = 0; i < 4; i++) {
            const float4 t = we4[(size_t)blk * 512 + i * 128 + tid];
            acc += t.x + t.y + t.z + t.w;
        }
        if (tid < 96) {
            const float4 t = reinterpret_cast<const float4*>(W_head)[(size_t)blk * 96 + tid];
            acc += t.x + t.y + t.z + t.w;
        }
    }

    float sum = v, sq = v * v;
    #pragma unroll
    for (int o = 16; o; o >>= 1) {
        sum += __shfl_xor_sync(0xffffffffu, sum, o);
        sq  += __shfl_xor_sync(0xffffffffu, sq,  o);
    }
    if (lane == 0) { sred[warp] = sum; sred[4 + warp] = sq; }
    __syncthreads();
    if (tid == 0) {
        g_red[b][seg][0] = (sred[0] + sred[1]) + (sred[2] + sred[3]);
        g_red[b][seg][1] = (sred[4] + sred[5]) + (sred[6] + sred[7]);
    }
    // keep the warm loads alive; never fires on finite inputs (deterministic)
    if (acc != acc) g_sink[0] = acc;
}

// ---------------------------------------------------------------------------
// K2: fused prologue (stats-finalize + xp + router) + per-expert smem GEMM.
// grid = (8 e, 4 b-tiles, 4 h-tiles), 256 threads.  warp w owns b = bt*8+w.
// smem layout (float4 units):
//   s_w   [64*65]  W tile            off 0
//   s_xp  [32*65]  xp rows           off 4160
//   s_wp  [256*5]  W_proj (padded)   off 6240
//   s_wr  [8*65]   W_router (padded) off 7520
//   s_be4 [16]     b_experts slice   off 8040
//   s_br4 [2]      b_router          off 8056
//   s_bp4 [64]     b_proj            off 8058
//   floats: s_xn[512], s_g[32]       off 8122 (f4)
// ---------------------------------------------------------------------------
#define K2_SMEM_BYTES (8258 * 16)

__global__ void __launch_bounds__(256)
k2_fused(const float* __restrict__ x,
         const float* __restrict__ W_proj,
         const float* __restrict__ b_proj,
         const float* __restrict__ W_router,
         const float* __restrict__ b_router,
         const float* __restrict__ W_experts,
         const float* __restrict__ b_experts) {
    extern __shared__ float4 smem4[];
    float4* s_w   = smem4;
    float4* s_xp  = smem4 + 4160;
    float4* s_wp  = smem4 + 6240;
    float4* s_wr  = smem4 + 7520;
    float4* s_be4 = smem4 + 8040;
    float4* s_br4 = smem4 + 8056;
    float4* s_bp4 = smem4 + 8058;
    float*  s_xn  = (float*)(smem4 + 8122);
    float*  s_g   = s_xn + 512;
    float*  s_xpf = (float*)s_xp;
    const float* s_bef = (const float*)s_be4;
    const float* s_brf = (const float*)s_br4;
    const float* s_bpf = (const float*)s_bp4;

    const int e   = blockIdx.x;
    const int bt  = blockIdx.y;
    const int htb = blockIdx.z;
    const int tid  = threadIdx.x;
    const int warp = tid >> 5;
    const int lane = tid & 31;
    const int b    = bt * 8 + warp;

    // ---- plain loads first (x values + stats partials) ----
    const float v0 = x[(size_t)b * LSEQ * CH + (size_t)lane * CH + 2];
    const float v1 = x[(size_t)b * LSEQ * CH + (size_t)(lane + 32) * CH + 2];
    float rs = 0.f, rq = 0.f;
    if (lane < 8) { rs = g_red[b][lane][0]; rq = g_red[b][lane][1]; }

    // ---- cp.async group0: small weights ----
    const float4* Wp4 = reinterpret_cast<const float4*>(W_proj);
    #pragma unroll
    for (int i = 0; i < 4; i++) {
        const int g = tid + 256 * i;
        cp16(&s_wp[(g >> 2) * 5 + (g & 3)], &Wp4[g]);
    }
    const float4* Wr4 = reinterpret_cast<const float4*>(W_router);
    #pragma unroll
    for (int i = 0; i < 2; i++) {
        const int g = tid + 256 * i;
        cp16(&s_wr[(g >> 6) * 65 + (g & 63)], &Wr4[g]);
    }
    if (tid < 16) cp16(&s_be4[tid],
                       reinterpret_cast<const float4*>(b_experts + e * D + htb * 64) + tid);
    if (tid < 2)  cp16(&s_br4[tid], reinterpret_cast<const float4*>(b_router) + tid);
    if (tid < 64) cp16(&s_bp4[tid], reinterpret_cast<const float4*>(b_proj) + tid);
    CP_COMMIT();

    // ---- cp.async group1: the big W tile ----
    const float4* Wg = reinterpret_cast<const float4*>(W_experts);
    #pragma unroll
    for (int r = 0; r < 16; r++) {
        const int flat = r * 256 + tid;
        const int row = flat >> 6, col = flat & 63;
        cp16(&s_w[row * 65 + col], &Wg[(size_t)(e * D + htb * 64 + row) * 64 + col]);
    }
    CP_COMMIT();

    // ---- finalize stats (per-warp, 8-lane shfl tree) ----
    #pragma unroll
    for (int o = 4; o; o >>= 1) {
        rs += __shfl_xor_sync(0xffffffffu, rs, o, 8);
        rq += __shfl_xor_sync(0xffffffffu, rq, o, 8);
    }
    rs = __shfl_sync(0xffffffffu, rs, 0);
    rq = __shfl_sync(0xffffffffu, rq, 0);
    const float mean = rs * (1.0f / LSEQ);
    const float var  = rq * (1.0f / LSEQ) - mean * mean;
    const float inv  = 1.0f / sqrtf(var + 1e-5f);

    s_xn[warp * 64 + lane]      = (v0 - mean) * inv;
    s_xn[warp * 64 + lane + 32] = (v1 - mean) * inv;

    CP_WAIT(1);          // group0 (small weights) complete on this thread
    __syncthreads();     // ... and on all threads; s_xn also visible

    // ---- xp: lane computes d = lane + 32*dd for its warp's b ----
    const float* xnw = s_xn + warp * 64;
    #pragma unroll
    for (int dd = 0; dd < 8; dd++) {
        const int d = lane + dd * 32;
        float w[PL];
        #pragma unroll
        for (int q = 0; q < 4; q++) {
            const float4 t = s_wp[d * 5 + q];
            w[q * 4 + 0] = t.x; w[q * 4 + 1] = t.y;
            w[q * 4 + 2] = t.z; w[q * 4 + 3] = t.w;
        }
        const float bp = s_bpf[d];
        #pragma unroll
        for (int p = 0; p < NP; p++) {
            float acc = bp;
            #pragma unroll
            for (int k = 0; k < PL; k++) acc = fmaf(w[k], xnw[p * PL + k], acc);
            s_xpf[(warp * 4 + p) * 260 + d] = acc;
        }
    }
    __syncwarp();

    // ---- router + softmax: lane = (p, ee) pair for this warp's b ----
    {
        const int p  = lane >> 3;
        const int ee = lane & 7;
        const float4* xrow = s_xp + (warp * 4 + p) * 65;
        const float4* wrow = s_wr + ee * 65;
        float a0 = 0.f, a1 = 0.f, a2 = 0.f, a3 = 0.f;
        #pragma unroll
        for (int k = 0; k < 64; k += 4) {
            const float4 w0 = wrow[k],     w1 = wrow[k + 1];
            const float4 w2 = wrow[k + 2], w3 = wrow[k + 3];
            const float4 x0 = xrow[k],     x1 = xrow[k + 1];
            const float4 x2 = xrow[k + 2], x3 = xrow[k + 3];
            a0 = fmaf(w0.x, x0.x, a0); a0 = fmaf(w0.y, x0.y, a0);
            a0 = fmaf(w0.z, x0.z, a0); a0 = fmaf(w0.w, x0.w, a0);
            a1 = fmaf(w1.x, x1.x, a1); a1 = fmaf(w1.y, x1.y, a1);
            a1 = fmaf(w1.z, x1.z, a1); a1 = fmaf(w1.w, x1.w, a1);
            a2 = fmaf(w2.x, x2.x, a2); a2 = fmaf(w2.y, x2.y, a2);
            a2 = fmaf(w2.z, x2.z, a2); a2 = fmaf(w2.w, x2.w, a2);
            a3 = fmaf(w3.x, x3.x, a3); a3 = fmaf(w3.y, x3.y, a3);
            a3 = fmaf(w3.z, x3.z, a3); a3 = fmaf(w3.w, x3.w, a3);
        }
        const float logit = (a0 + a1) + (a2 + a3) + s_brf[ee];
        float m = logit;
        #pragma unroll
        for (int o = 4; o; o >>= 1) m = fmaxf(m, __shfl_xor_sync(0xffffffffu, m, o, 8));
        const float exv = __expf(logit - m);
        float den = exv;
        #pragma unroll
        for (int o = 4; o; o >>= 1) den += __shfl_xor_sync(0xffffffffu, den, o, 8);
        if (ee == e) s_g[warp * 4 + p] = exv / den;
    }

    CP_WAIT(0);          // W tile resident
    __syncthreads();

    // ---- GEMM: thread = (rt row-tile, ht strided-h, kh K-half) ----
    const int kh = tid & 1;
    const int ht = (tid >> 1) & 15;
    const int rt = tid >> 5;

    float acc[4][4];
    #pragma unroll
    for (int i = 0; i < 4; i++)
        #pragma unroll
        for (int j = 0; j < 4; j++) acc[i][j] = 0.f;

    const float4* xb4 = s_xp + rt * 4 * 65 + kh * 32;
    const float4* wb4 = s_w  + ht * 65     + kh * 32;

    #pragma unroll 4
    for (int kk = 0; kk < 32; kk++) {
        const float4 x0 = xb4[0 * 65 + kk];
        const float4 x1 = xb4[1 * 65 + kk];
        const float4 x2 = xb4[2 * 65 + kk];
        const float4 x3 = xb4[3 * 65 + kk];
        const float4 w0 = wb4[0 * 1040 + kk];
        const float4 w1 = wb4[1 * 1040 + kk];
        const float4 w2 = wb4[2 * 1040 + kk];
        const float4 w3 = wb4[3 * 1040 + kk];
        #pragma unroll
        for (int i = 0; i < 4; i++) {
            const float4 xv = (i == 0) ? x0 : (i == 1) ? x1 : (i == 2) ? x2 : x3;
            acc[i][0] = fmaf(xv.x, w0.x, acc[i][0]); acc[i][0] = fmaf(xv.y, w0.y, acc[i][0]);
            acc[i][0] = fmaf(xv.z, w0.z, acc[i][0]); acc[i][0] = fmaf(xv.w, w0.w, acc[i][0]);
            acc[i][1] = fmaf(xv.x, w1.x, acc[i][1]); acc[i][1] = fmaf(xv.y, w1.y, acc[i][1]);
            acc[i][1] = fmaf(xv.z, w1.z, acc[i][1]); acc[i][1] = fmaf(xv.w, w1.w, acc[i][1]);
            acc[i][2] = fmaf(xv.x, w2.x, acc[i][2]); acc[i][2] = fmaf(xv.y, w2.y, acc[i][2]);
            acc[i][2] = fmaf(xv.z, w2.z, acc[i][2]); acc[i][2] = fmaf(xv.w, w2.w, acc[i][2]);
            acc[i][3] = fmaf(xv.x, w3.x, acc[i][3]); acc[i][3] = fmaf(xv.y, w3.y, acc[i][3]);
            acc[i][3] = fmaf(xv.z, w3.z, acc[i][3]); acc[i][3] = fmaf(xv.w, w3.w, acc[i][3]);
        }
    }

    #pragma unroll
    for (int i = 0; i < 4; i++)
        #pragma unroll
        for (int j = 0; j < 4; j++)
            acc[i][j] += __shfl_xor_sync(0xffffffffu, acc[i][j], 1);

    if (kh == 0) {
        #pragma unroll
        for (int i = 0; i < 4; i++) {
            const int r  = rt * 4 + i;
            const int bb = bt * 8 + (r >> 2);
            const int p  = r & 3;
            const float g = s_g[r];
            #pragma unroll
            for (int j = 0; j < 4; j++) {
                const int hl = ht + j * 16;
                g_partial[bb][e][p * D + htb * 64 + hl] = g * (acc[i][j] + s_bef[hl]);
            }
        }
    }
}

// ---------------------------------------------------------------------------
// K3: combine 8 experts + de-normalize + head matvec.
// grid = (32 b, 12 t-tiles), 256 threads; 8 warps -> 8 outputs per block.
// ---------------------------------------------------------------------------
__global__ void __launch_bounds__(256)
k3_head(const float* __restrict__ W_head,
        const float* __restrict__ b_head,
        float* __restrict__ out) {
    const int b    = blockIdx.x;
    const int tid  = threadIdx.x;
    const int warp = tid >> 5;
    const int lane = tid & 31;

    __shared__ __align__(16) float s_t[LSEQ];

    // independent combine loads first (8 L2-hot LDG.128 in flight)
    const float4* gp = reinterpret_cast<const float4*>(&g_partial[b][0][0]);
    float4 v[NE];
    #pragma unroll
    for (int e = 0; e < NE; e++) v[e] = gp[e * 256 + tid];

    // stats recompute (uniform-address, warp-broadcast loads) overlaps above
    float ts = 0.f, tq = 0.f;
    #pragma unroll
    for (int s = 0; s < 8; s++) { ts += g_red[b][s][0]; tq += g_red[b][s][1]; }
    const float mean = ts * (1.0f / LSEQ);
    const float sd   = sqrtf(tq * (1.0f / LSEQ) - mean * mean + 1e-5f);

    float4 acc = v[0];
    #pragma unroll
    for (int e = 1; e < NE; e++) {
        acc.x += v[e].x; acc.y += v[e].y; acc.z += v[e].z; acc.w += v[e].w;
    }
    reinterpret_cast<float4*>(s_t)[tid] =
        make_float4(fmaf(acc.x, sd, mean), fmaf(acc.y, sd, mean),
                    fmaf(acc.z, sd, mean), fmaf(acc.w, sd, mean));
    __syncthreads();

    const int t = blockIdx.y * 8 + warp;
    const float4* wr = reinterpret_cast<const float4*>(W_head + (size_t)t * LSEQ);
    const float4* tt = reinterpret_cast<const float4*>(s_t);
    float ax = 0.f, ay = 0.f, az = 0.f, aw = 0.f;
    #pragma unroll
    for (int q = 0; q < 8; q++) {
        const int i = q * 32 + lane;
        const float4 w = wr[i];
        const float4 f = tt[i];
        ax = fmaf(w.x, f.x, ax);
        ay = fmaf(w.y, f.y, ay);
        az = fmaf(w.z, f.z, az);
        aw = fmaf(w.w, f.w, aw);
    }
    float r = (ax + ay) + (az + aw);
    #pragma unroll
    for (int o = 16; o; o >>= 1) r += __shfl_xor_sync(0xffffffffu, r, o);
    if (lane == 0) out[b * PRED + t] = r + b_head[t];
}

// ---------------------------------------------------------------------------
extern "C" void kernel_launch(void* const* d_in, const int* in_sizes, int n_in,
                              void* d_out, int out_size) {
    const float* x         = (const float*)d_in[0];
    const float* W_proj    = (const float*)d_in[4];
    const float* b_proj    = (const float*)d_in[5];
    const float* W_router  = (const float*)d_in[6];
    const float* b_router  = (const float*)d_in[7];
    const float* W_experts = (const float*)d_in[8];
    const float* b_experts = (const float*)d_in[9];
    const float* W_head    = (const float*)d_in[10];
    const float* b_head    = (const float*)d_in[11];
    float* out = (float*)d_out;

    cudaFuncSetAttribute(k2_fused,
                         cudaFuncAttributeMaxDynamicSharedMemorySize,
                         K2_SMEM_BYTES);

    k0_stats<<<NB * 8, 128>>>(x, W_experts, W_head);
    dim3 g2(NE, NB / 8, NP);
    k2_fused<<<g2, 256, K2_SMEM_BYTES>>>(x, W_proj, b_proj, W_router, b_router,
                                         W_experts, b_experts);
    dim3 g3(NB, PRED / 8);
    k3_head<<<g3, 256>>>(W_head, b_head, out);
}